// round 9
// baseline (speedup 1.0000x reference)
#include <cuda_runtime.h>
#include <cstdint>

// LmulLinear: out[m,p] = sum_k bitcast_f32(bits(x[m,k]) + bits(w[p,k]) - OFFSET) + bias[p]
// M=256, K=512, P=512.
//
// R9: R5's GEMM shape (512 CTAs x 256 thr, BM=BN=32, KSPLIT=4, 2x2 microtile,
//     best measured issue efficiency) with k-paired add.rn.f32x2 accumulation
//     (1.75 issues/MAC) + light reduce kernel.

#define M_DIM 256
#define K_DIM 512
#define P_DIM 512
#define BM 32
#define BN 32
#define KSPLIT 4
#define KG (K_DIM / KSPLIT)        // 128 k per CTA
#define SROW (KG + 4)              // 132 words
#define TILE_WORDS (BM * SROW)     // 4224 words
#define SMEM_BYTES (2 * TILE_WORDS * 4)   // 33792 B (static)

__device__ float g_partial[KSPLIT * M_DIM * P_DIM];   // 2 MB, L2-resident

// accpair(f32x2) += ( f32(ax+bx), f32(ay+by) )   [two consecutive k's, same output]
#define LMAC2(acc, ax, bx, ay, by)                                             \
    asm("{\n\t"                                                                \
        ".reg .b32 lo, hi;\n\t"                                                \
        ".reg .b64 t;\n\t"                                                     \
        "add.u32 lo, %1, %2;\n\t"                                              \
        "add.u32 hi, %3, %4;\n\t"                                              \
        "mov.b64 t, {lo, hi};\n\t"                                             \
        "add.rn.f32x2 %0, %0, t;\n\t"                                          \
        "}" : "+l"(acc) : "r"(ax), "r"(bx), "r"(ay), "r"(by))

static __device__ __forceinline__ float hsum2(uint64_t acc) {
    uint32_t lo, hi;
    asm("mov.b64 {%0, %1}, %2;" : "=r"(lo), "=r"(hi) : "l"(acc));
    return __uint_as_float(lo) + __uint_as_float(hi);
}

__global__ void __launch_bounds__(256)
lmul_partial_kernel(const float* __restrict__ x,
                    const float* __restrict__ w)
{
    constexpr uint32_t OFFSET = 1064828928u;  // 0x3F780000

    __shared__ uint32_t As[TILE_WORDS];   // [BM][SROW]
    __shared__ uint32_t Bs[TILE_WORDS];   // [BN][SROW], offset-folded

    const int tid = threadIdx.x;
    const int tx  = tid & 15;        // p cols: tx, tx+16
    const int ty  = tid >> 4;        // m rows: ty, ty+16
    const int m0  = blockIdx.y * BM;
    const int p0  = blockIdx.x * BN;
    const int kbase = blockIdx.z * KG;

    const uint32_t* __restrict__ xu = reinterpret_cast<const uint32_t*>(x);
    const uint32_t* __restrict__ wu = reinterpret_cast<const uint32_t*>(w);

    // ---- load tiles: each 32 rows x 32 uint4 = 1024 uint4; 4 per thread per tile ----
    #pragma unroll
    for (int i = 0; i < 4; i++) {
        int idx = tid + i * 256;        // 0..1023
        int row = idx >> 5;
        int c   = (idx & 31) * 4;
        uint4 va = *reinterpret_cast<const uint4*>(&xu[(m0 + row) * K_DIM + kbase + c]);
        *reinterpret_cast<uint4*>(&As[row * SROW + c]) = va;
        uint4 vb = *reinterpret_cast<const uint4*>(&wu[(p0 + row) * K_DIM + kbase + c]);
        vb.x -= OFFSET; vb.y -= OFFSET; vb.z -= OFFSET; vb.w -= OFFSET;
        *reinterpret_cast<uint4*>(&Bs[row * SROW + c]) = vb;
    }
    __syncthreads();

    // ---- 2x2 microtile: rows {ty, ty+16}, cols {tx, tx+16}; f32x2 k-paired accs ----
    const uint32_t* a0p = As + ty * SROW;
    const uint32_t* a1p = As + (ty + 16) * SROW;
    const uint32_t* b0p = Bs + tx * SROW;
    const uint32_t* b1p = Bs + (tx + 16) * SROW;

    uint64_t acc00 = 0ull, acc01 = 0ull, acc10 = 0ull, acc11 = 0ull;

    #pragma unroll 8
    for (int j = 0; j < KG / 4; j++) {
        uint4 a0 = *reinterpret_cast<const uint4*>(a0p + 4 * j);
        uint4 a1 = *reinterpret_cast<const uint4*>(a1p + 4 * j);
        uint4 b0 = *reinterpret_cast<const uint4*>(b0p + 4 * j);
        uint4 b1 = *reinterpret_cast<const uint4*>(b1p + 4 * j);

        LMAC2(acc00, a0.x, b0.x, a0.y, b0.y);
        LMAC2(acc00, a0.z, b0.z, a0.w, b0.w);
        LMAC2(acc01, a0.x, b1.x, a0.y, b1.y);
        LMAC2(acc01, a0.z, b1.z, a0.w, b1.w);
        LMAC2(acc10, a1.x, b0.x, a1.y, b0.y);
        LMAC2(acc10, a1.z, b0.z, a1.w, b0.w);
        LMAC2(acc11, a1.x, b1.x, a1.y, b1.y);
        LMAC2(acc11, a1.z, b1.z, a1.w, b1.w);
    }

    // ---- fold pairs, write partials (coalesced), skip L1 ----
    float* part = g_partial + blockIdx.z * (M_DIM * P_DIM);
    const int m_a = m0 + ty;
    const int m_b = m0 + ty + 16;
    __stcg(&part[m_a * P_DIM + p0 + tx],      hsum2(acc00));
    __stcg(&part[m_a * P_DIM + p0 + tx + 16], hsum2(acc01));
    __stcg(&part[m_b * P_DIM + p0 + tx],      hsum2(acc10));
    __stcg(&part[m_b * P_DIM + p0 + tx + 16], hsum2(acc11));
}

__global__ void __launch_bounds__(128)
lmul_reduce_kernel(const float* __restrict__ bias,
                   float* __restrict__ out)
{
    // 32768 float4 outputs; 256 CTAs x 128 threads, one float4 each, MLP=5.
    const int idx4 = blockIdx.x * 128 + threadIdx.x;   // 0..32767
    const int base = idx4 * 4;
    const int p = base & (P_DIM - 1);

    float4 v0 = __ldcg(reinterpret_cast<const float4*>(g_partial + 0 * M_DIM * P_DIM + base));
    float4 v1 = __ldcg(reinterpret_cast<const float4*>(g_partial + 1 * M_DIM * P_DIM + base));
    float4 v2 = __ldcg(reinterpret_cast<const float4*>(g_partial + 2 * M_DIM * P_DIM + base));
    float4 v3 = __ldcg(reinterpret_cast<const float4*>(g_partial + 3 * M_DIM * P_DIM + base));
    float4 b  = __ldg(reinterpret_cast<const float4*>(bias + p));

    float4 r;
    r.x = ((v0.x + v1.x) + (v2.x + v3.x)) + b.x;
    r.y = ((v0.y + v1.y) + (v2.y + v3.y)) + b.y;
    r.z = ((v0.z + v1.z) + (v2.z + v3.z)) + b.z;
    r.w = ((v0.w + v1.w) + (v2.w + v3.w)) + b.w;

    *reinterpret_cast<float4*>(out + base) = r;
}

extern "C" void kernel_launch(void* const* d_in, const int* in_sizes, int n_in,
                              void* d_out, int out_size)
{
    const float* x    = (const float*)d_in[0];   // (256, 512)
    const float* w    = (const float*)d_in[1];   // (512, 512)
    const float* bias = (const float*)d_in[2];   // (512,)
    float* out = (float*)d_out;                  // (256, 512)

    dim3 grid1(P_DIM / BN, M_DIM / BM, KSPLIT);  // (16, 8, 4) = 512 CTAs
    lmul_partial_kernel<<<grid1, 256>>>(x, w);

    dim3 grid2((M_DIM * P_DIM) / (128 * 4));     // 256 CTAs
    lmul_reduce_kernel<<<grid2, 128>>>(bias, out);
}

// round 10
// speedup vs baseline: 1.1575x; 1.1575x over previous
#include <cuda_runtime.h>
#include <cstdint>

// LmulLinear: out[m,p] = sum_k bitcast_f32(bits(x[m,k]) + bits(w[p,k]) - OFFSET) + bias[p]
// M=256, K=512, P=512.
//
// R10: smem-wavefront-lean GEMM: 4x4 microtile, BM=BN=64, 256 thr, KSPLIT=8
//      (0.1875 wf/MAC, 2.125 issues/MAC, L0-resident loop) + reduce kernel.

#define M_DIM 256
#define K_DIM 512
#define P_DIM 512
#define BM 64
#define BN 64
#define KSPLIT 8
#define KG (K_DIM / KSPLIT)        // 64 k per CTA
#define SROW (KG + 4)              // 68 words; 68/4=17 odd -> conflict-free LDS.128
#define TILE_WORDS (BM * SROW)     // 4352 words per tile (17408 B)

__device__ float g_partial[KSPLIT * M_DIM * P_DIM];   // 4 MB, L2-resident

static __device__ __forceinline__ float u2f(uint32_t u) { return __uint_as_float(u); }

__global__ void __launch_bounds__(256)
lmul_partial_kernel(const float* __restrict__ x,
                    const float* __restrict__ w)
{
    constexpr uint32_t OFFSET = 1064828928u;  // 0x3F780000

    __shared__ uint32_t As[TILE_WORDS];   // [BM][SROW]
    __shared__ uint32_t Bs[TILE_WORDS];   // [BN][SROW], offset-folded

    const int tid = threadIdx.x;
    const int tx  = tid & 15;        // p cols: tx + 16c, c<4
    const int ty  = tid >> 4;        // m rows: ty + 16r, r<4
    const int m0  = blockIdx.y * BM;
    const int p0  = blockIdx.x * BN;
    const int kbase = blockIdx.z * KG;

    const uint32_t* __restrict__ xu = reinterpret_cast<const uint32_t*>(x);
    const uint32_t* __restrict__ wu = reinterpret_cast<const uint32_t*>(w);

    // ---- load tiles: each 64 rows x 16 uint4 = 1024 uint4; 4 per thread per tile ----
    #pragma unroll
    for (int i = 0; i < 4; i++) {
        int idx = tid + i * 256;        // 0..1023
        int row = idx >> 4;             // 16 uint4 per row
        int c   = (idx & 15) * 4;
        uint4 va = *reinterpret_cast<const uint4*>(&xu[(m0 + row) * K_DIM + kbase + c]);
        *reinterpret_cast<uint4*>(&As[row * SROW + c]) = va;
        uint4 vb = *reinterpret_cast<const uint4*>(&wu[(p0 + row) * K_DIM + kbase + c]);
        vb.x -= OFFSET; vb.y -= OFFSET; vb.z -= OFFSET; vb.w -= OFFSET;
        *reinterpret_cast<uint4*>(&Bs[row * SROW + c]) = vb;
    }
    __syncthreads();

    // ---- 4x4 microtile: rows {ty+16r}, cols {tx+16c} ----
    const uint32_t* ap = As + ty * SROW;
    const uint32_t* bp = Bs + tx * SROW;

    float acc[4][4];
    #pragma unroll
    for (int r = 0; r < 4; r++)
        #pragma unroll
        for (int c = 0; c < 4; c++) acc[r][c] = 0.f;

    #pragma unroll 2
    for (int j = 0; j < KG / 4; j++) {
        uint4 a[4], b[4];
        #pragma unroll
        for (int r = 0; r < 4; r++)
            a[r] = *reinterpret_cast<const uint4*>(ap + (16 * r) * SROW + 4 * j);
        #pragma unroll
        for (int c = 0; c < 4; c++)
            b[c] = *reinterpret_cast<const uint4*>(bp + (16 * c) * SROW + 4 * j);

        #pragma unroll
        for (int r = 0; r < 4; r++) {
            #pragma unroll
            for (int c = 0; c < 4; c++) {
                acc[r][c] += u2f(a[r].x + b[c].x);
                acc[r][c] += u2f(a[r].y + b[c].y);
                acc[r][c] += u2f(a[r].z + b[c].z);
                acc[r][c] += u2f(a[r].w + b[c].w);
            }
        }
    }

    // ---- write partials (coalesced 16-lane runs), skip L1 ----
    float* part = g_partial + blockIdx.z * (M_DIM * P_DIM);
    #pragma unroll
    for (int r = 0; r < 4; r++) {
        const int m = m0 + ty + 16 * r;
        #pragma unroll
        for (int c = 0; c < 4; c++)
            __stcg(&part[m * P_DIM + p0 + tx + 16 * c], acc[r][c]);
    }
}

__global__ void __launch_bounds__(128)
lmul_reduce_kernel(const float* __restrict__ bias,
                   float* __restrict__ out)
{
    // 32768 float4 outputs; 256 CTAs x 128 threads, one float4 each, MLP=9.
    const int idx4 = blockIdx.x * 128 + threadIdx.x;   // 0..32767
    const int base = idx4 * 4;
    const int p = base & (P_DIM - 1);

    float4 v[KSPLIT];
    #pragma unroll
    for (int k = 0; k < KSPLIT; k++)
        v[k] = __ldcg(reinterpret_cast<const float4*>(g_partial + k * (M_DIM * P_DIM) + base));
    float4 b = __ldg(reinterpret_cast<const float4*>(bias + p));

    float4 r = v[0];
    #pragma unroll
    for (int k = 1; k < KSPLIT; k++) {
        r.x += v[k].x; r.y += v[k].y; r.z += v[k].z; r.w += v[k].w;
    }
    r.x += b.x; r.y += b.y; r.z += b.z; r.w += b.w;

    *reinterpret_cast<float4*>(out + base) = r;
}

extern "C" void kernel_launch(void* const* d_in, const int* in_sizes, int n_in,
                              void* d_out, int out_size)
{
    const float* x    = (const float*)d_in[0];   // (256, 512)
    const float* w    = (const float*)d_in[1];   // (512, 512)
    const float* bias = (const float*)d_in[2];   // (512,)
    float* out = (float*)d_out;                  // (256, 512)

    dim3 grid1(P_DIM / BN, M_DIM / BM, KSPLIT);  // (8, 4, 8) = 256 CTAs
    lmul_partial_kernel<<<grid1, 256>>>(x, w);

    dim3 grid2((M_DIM * P_DIM) / (128 * 4));     // 256 CTAs
    lmul_reduce_kernel<<<grid2, 128>>>(bias, out);
}

// round 11
// speedup vs baseline: 1.1604x; 1.0025x over previous
#include <cuda_runtime.h>
#include <cstdint>

// LmulLinear: out[m,p] = sum_k bitcast_f32(bits(x[m,k]) + bits(w[p,k]) - OFFSET) + bias[p]
// M=256, K=512, P=512.
//
// R11: SINGLE kernel. 128 CTAs x 512 thr = 4 k-groups x 128 thr.
//      BM=BN=32, 2x4 microtile (2.19 issues/MAC, all-1-wavefront LDS),
//      smem tree reduction epilogue. No scratch, no second launch, no fences.

#define M_DIM 256
#define K_DIM 512
#define P_DIM 512
#define BM 32
#define BN 32
#define GROUPS 4
#define KG (K_DIM / GROUPS)        // 128 k per group
#define TPG 128                    // threads per group
#define SROW (KG + 4)              // 132 words
#define TILE_WORDS (BM * SROW)     // 4224 words per tile
#define GROUP_WORDS (2 * TILE_WORDS)
#define SMEM_BYTES (GROUPS * GROUP_WORDS * 4)   // 135168 B

static __device__ __forceinline__ float u2f(uint32_t u) { return __uint_as_float(u); }

extern __shared__ uint32_t smem[];

__global__ void __launch_bounds__(512, 1)
lmul_linear_kernel(const float* __restrict__ x,
                   const float* __restrict__ w,
                   const float* __restrict__ bias,
                   float* __restrict__ out)
{
    constexpr uint32_t OFFSET = 1064828928u;  // 0x3F780000

    const int tid = threadIdx.x;
    const int g   = tid >> 7;        // k-group 0..3
    const int lt  = tid & 127;       // lane in group
    const int tx  = lt & 7;          // p cols: tx + 8c, c<4
    const int ty  = lt >> 3;         // m rows: ty, ty+16
    const int m0  = blockIdx.y * BM;
    const int p0  = blockIdx.x * BN;
    const int kbase = g * KG;

    uint32_t* As = smem + g * GROUP_WORDS;   // [BM][SROW]
    uint32_t* Bs = As + TILE_WORDS;          // [BN][SROW], offset-folded

    const uint32_t* __restrict__ xu = reinterpret_cast<const uint32_t*>(x);
    const uint32_t* __restrict__ wu = reinterpret_cast<const uint32_t*>(w);

    // ---- load this group's tiles: 32 rows x 32 uint4 each; 8 uint4/thread/tile ----
    #pragma unroll
    for (int i = 0; i < 8; i++) {
        int idx  = lt + i * TPG;        // 0..1023
        int row  = idx >> 5;
        int col4 = idx & 31;            // uint4 index within row
        uint4 va = *reinterpret_cast<const uint4*>(&xu[(m0 + row) * K_DIM + kbase + col4 * 4]);
        *reinterpret_cast<uint4*>(&As[row * SROW + col4 * 4]) = va;
        uint4 vb = *reinterpret_cast<const uint4*>(&wu[(p0 + row) * K_DIM + kbase + col4 * 4]);
        vb.x -= OFFSET; vb.y -= OFFSET; vb.z -= OFFSET; vb.w -= OFFSET;
        *reinterpret_cast<uint4*>(&Bs[row * SROW + col4 * 4]) = vb;
    }
    __syncthreads();

    // ---- main loop: 2x4 microtile, rows {ty, ty+16}, cols {tx+8c} ----
    const uint32_t* a0p = As + ty * SROW;
    const uint32_t* a1p = As + (ty + 16) * SROW;
    const uint32_t* bp  = Bs + tx * SROW;

    float acc[2][4];
    #pragma unroll
    for (int r = 0; r < 2; r++)
        #pragma unroll
        for (int c = 0; c < 4; c++) acc[r][c] = 0.f;

    #pragma unroll 4
    for (int j = 0; j < KG / 4; j++) {
        uint4 a0 = *reinterpret_cast<const uint4*>(a0p + 4 * j);
        uint4 a1 = *reinterpret_cast<const uint4*>(a1p + 4 * j);
        uint4 b[4];
        #pragma unroll
        for (int c = 0; c < 4; c++)
            b[c] = *reinterpret_cast<const uint4*>(bp + (8 * c) * SROW + 4 * j);

        #pragma unroll
        for (int c = 0; c < 4; c++) {
            acc[0][c] += u2f(a0.x + b[c].x);
            acc[1][c] += u2f(a1.x + b[c].x);
            acc[0][c] += u2f(a0.y + b[c].y);
            acc[1][c] += u2f(a1.y + b[c].y);
            acc[0][c] += u2f(a0.z + b[c].z);
            acc[1][c] += u2f(a1.z + b[c].z);
            acc[0][c] += u2f(a0.w + b[c].w);
            acc[1][c] += u2f(a1.w + b[c].w);
        }
    }

    // ---- tree reduction across k-groups in smem (reuse tile space) ----
    float* Red = reinterpret_cast<float*>(smem);   // [3][128][8] floats = 12 KB

    __syncthreads();   // tiles fully consumed
    if (g > 0) {
        float* rr = Red + ((g - 1) * TPG + lt) * 8;
        #pragma unroll
        for (int r = 0; r < 2; r++)
            #pragma unroll
            for (int c = 0; c < 4; c++) rr[r * 4 + c] = acc[r][c];
    }
    __syncthreads();

    if (g == 0) {
        #pragma unroll
        for (int gg = 0; gg < 3; gg++) {
            const float* rr = Red + (gg * TPG + lt) * 8;
            #pragma unroll
            for (int r = 0; r < 2; r++)
                #pragma unroll
                for (int c = 0; c < 4; c++) acc[r][c] += rr[r * 4 + c];
        }

        #pragma unroll
        for (int c = 0; c < 4; c++) {
            const float bv = bias[p0 + tx + 8 * c];
            acc[0][c] += bv;
            acc[1][c] += bv;
        }

        #pragma unroll
        for (int r = 0; r < 2; r++) {
            const int m = m0 + ty + 16 * r;
            float* orow = out + m * P_DIM + p0;
            #pragma unroll
            for (int c = 0; c < 4; c++)
                orow[tx + 8 * c] = acc[r][c];
        }
    }
}

extern "C" void kernel_launch(void* const* d_in, const int* in_sizes, int n_in,
                              void* d_out, int out_size)
{
    const float* x    = (const float*)d_in[0];   // (256, 512)
    const float* w    = (const float*)d_in[1];   // (512, 512)
    const float* bias = (const float*)d_in[2];   // (512,)
    float* out = (float*)d_out;                  // (256, 512)

    cudaFuncSetAttribute(lmul_linear_kernel,
                         cudaFuncAttributeMaxDynamicSharedMemorySize, SMEM_BYTES);

    dim3 grid(P_DIM / BN, M_DIM / BM);   // (16, 8) = 128 CTAs
    lmul_linear_kernel<<<grid, 512, SMEM_BYTES>>>(x, w, bias, out);
}